// round 1
// baseline (speedup 1.0000x reference)
#include <cuda_runtime.h>
#include <cstdint>

#define B_  16
#define N_  1024
#define O_  64
#define H_  1024
#define D_  256

#define MV  (B_ * N_)
#define MP  (B_ * O_)

#define LOG_OFF  0
#define ATT_OFF  (B_ * O_)
#define EV_OFF   (ATT_OFF + B_ * O_ * N_)
#define LOSS_OFF (EV_OFF + B_ * O_ * D_)

__device__ float g_visual[MV * D_];
__device__ float g_phrase[MP * D_];
__device__ float g_protoN[MP * D_];
__device__ float g_accum[2];

__global__ void k_zero() { g_accum[0] = 0.0f; g_accum[1] = 0.0f; }

#define BM 128
#define BN 64
#define BK 16

__global__ __launch_bounds__(256) void k_gemm_bias(
    const float* __restrict__ A, const float* __restrict__ W,
    const float* __restrict__ bias, float* __restrict__ C, int M, int K, int Nd)
{
    __shared__ float As[BK][BM];
    __shared__ float Bs[BK][BN];

    const int tid = threadIdx.x;
    const int bm = blockIdx.y * BM;
    const int bn = blockIdx.x * BN;
    const int ty = tid / 16;
    const int tx = tid % 16;
    const int arow = tid / 4;
    const int acol = (tid % 4) * 4;
    const int brow = tid / 16;
    const int bcol = (tid % 16) * 4;

    float acc[8][4];
    #pragma unroll
    for (int i = 0; i < 8; i++)
        #pragma unroll
        for (int j = 0; j < 4; j++) acc[i][j] = 0.0f;

    for (int k0 = 0; k0 < K; k0 += BK) {
        #pragma unroll
        for (int h = 0; h < 2; h++) {
            const int r = arow + h * 64;
            const float4 a = *(const float4*)&A[(size_t)(bm + r) * K + k0 + acol];
            As[acol + 0][r] = a.x;
            As[acol + 1][r] = a.y;
            As[acol + 2][r] = a.z;
            As[acol + 3][r] = a.w;
        }
        const float4 b4 = *(const float4*)&W[(size_t)(k0 + brow) * Nd + bn + bcol];
        *(float4*)&Bs[brow][bcol] = b4;
        __syncthreads();

        #pragma unroll
        for (int k = 0; k < BK; k++) {
            float4 a0 = *(float4*)&As[k][ty * 8];
            float4 a1 = *(float4*)&As[k][ty * 8 + 4];
            float4 bb = *(float4*)&Bs[k][tx * 4];
            const float av[8] = {a0.x, a0.y, a0.z, a0.w, a1.x, a1.y, a1.z, a1.w};
            const float bw[4] = {bb.x, bb.y, bb.z, bb.w};
            #pragma unroll
            for (int i = 0; i < 8; i++)
                #pragma unroll
                for (int j = 0; j < 4; j++)
                    acc[i][j] = fmaf(av[i], bw[j], acc[i][j]);
        }
        __syncthreads();
    }

    const float4 bias4 = *(const float4*)&bias[bn + tx * 4];
    #pragma unroll
    for (int i = 0; i < 8; i++) {
        const int m = bm + ty * 8 + i;
        float4 r;
        r.x = acc[i][0] + bias4.x;
        r.y = acc[i][1] + bias4.y;
        r.z = acc[i][2] + bias4.z;
        r.w = acc[i][3] + bias4.w;
        *(float4*)&C[(size_t)m * Nd + bn + tx * 4] = r;
    }
}

__device__ __forceinline__ float warp_sum(float v) {
    #pragma unroll
    for (int o = 16; o > 0; o >>= 1) v += __shfl_xor_sync(0xffffffffu, v, o);
    return v;
}
__device__ __forceinline__ float warp_max(float v) {
    #pragma unroll
    for (int o = 16; o > 0; o >>= 1) v = fmaxf(v, __shfl_xor_sync(0xffffffffu, v, o));
    return v;
}

__global__ __launch_bounds__(256) void k_norm_visual() {
    const int wid = threadIdx.x / 32;
    const int lane = threadIdx.x % 32;
    const int row = blockIdx.x * 8 + wid;
    float* p = g_visual + (size_t)row * D_;

    float4 x0 = *(float4*)&p[lane * 4];
    float4 x1 = *(float4*)&p[128 + lane * 4];
    float s = x0.x * x0.x + x0.y * x0.y + x0.z * x0.z + x0.w * x0.w
            + x1.x * x1.x + x1.y * x1.y + x1.z * x1.z + x1.w * x1.w;
    s = warp_sum(s);
    const float inv = 1.0f / fmaxf(sqrtf(s), 1e-12f);
    x0.x *= inv; x0.y *= inv; x0.z *= inv; x0.w *= inv;
    x1.x *= inv; x1.y *= inv; x1.z *= inv; x1.w *= inv;
    *(float4*)&p[lane * 4] = x0;
    *(float4*)&p[128 + lane * 4] = x1;
}

__global__ __launch_bounds__(256) void k_phrase_proto(const float* __restrict__ proto) {
    const int wid = threadIdx.x / 32;
    const int lane = threadIdx.x % 32;
    const int row = blockIdx.x * 8 + wid;
    const int o = row % O_;
    float* pp = g_phrase + (size_t)row * D_;

    float4 x0 = *(float4*)&pp[lane * 4];
    float4 x1 = *(float4*)&pp[128 + lane * 4];
    float s = x0.x * x0.x + x0.y * x0.y + x0.z * x0.z + x0.w * x0.w
            + x1.x * x1.x + x1.y * x1.y + x1.z * x1.z + x1.w * x1.w;
    s = warp_sum(s);
    const float inv = 1.0f / fmaxf(sqrtf(s), 1e-12f);
    x0.x *= inv; x0.y *= inv; x0.z *= inv; x0.w *= inv;
    x1.x *= inv; x1.y *= inv; x1.z *= inv; x1.w *= inv;
    *(float4*)&pp[lane * 4] = x0;
    *(float4*)&pp[128 + lane * 4] = x1;

    const float4 q0g = *(const float4*)&proto[(size_t)o * D_ + lane * 4];
    const float4 q1g = *(const float4*)&proto[(size_t)o * D_ + 128 + lane * 4];
    float4 q0, q1;
    q0.x = q0g.x + x0.x; q0.y = q0g.y + x0.y; q0.z = q0g.z + x0.z; q0.w = q0g.w + x0.w;
    q1.x = q1g.x + x1.x; q1.y = q1g.y + x1.y; q1.z = q1g.z + x1.z; q1.w = q1g.w + x1.w;
    float s2 = q0.x * q0.x + q0.y * q0.y + q0.z * q0.z + q0.w * q0.w
             + q1.x * q1.x + q1.y * q1.y + q1.z * q1.z + q1.w * q1.w;
    s2 = warp_sum(s2);
    const float inv2 = 1.0f / fmaxf(sqrtf(s2), 1e-12f);
    q0.x *= inv2; q0.y *= inv2; q0.z *= inv2; q0.w *= inv2;
    q1.x *= inv2; q1.y *= inv2; q1.z *= inv2; q1.w *= inv2;
    float* pn = g_protoN + (size_t)row * D_;
    *(float4*)&pn[lane * 4] = q0;
    *(float4*)&pn[128 + lane * 4] = q1;
}

__global__ __launch_bounds__(256) void k_attention(
    const float* __restrict__ labels, const float* __restrict__ Wc,
    const float* __restrict__ bcp, float* __restrict__ out)
{
    __shared__ float sp[8][D_];
    __shared__ float attn_s[8][N_];
    __shared__ float s_red[8];
    __shared__ float s_ent;

    const int tid = threadIdx.x;
    const int og = blockIdx.x;
    const int b  = blockIdx.y;
    const int wid = tid / 32, lane = tid % 32;
    const int row0 = b * O_ + og * 8;

    #pragma unroll
    for (int i = 0; i < 8; i++)
        sp[i][tid] = g_protoN[(size_t)(row0 + i) * D_ + tid];
    if (tid == 0) s_ent = 0.0f;
    __syncthreads();

    {
        const float* v0 = g_visual + ((size_t)(b * N_ + tid)) * D_;
        const float* v1 = v0 + 256 * D_;
        const float* v2 = v1 + 256 * D_;
        const float* v3 = v2 + 256 * D_;
        float acc[8][4];
        #pragma unroll
        for (int o = 0; o < 8; o++)
            #pragma unroll
            for (int i = 0; i < 4; i++) acc[o][i] = 0.0f;

        #pragma unroll 4
        for (int d = 0; d < D_; d++) {
            const float a = v0[d], b2 = v1[d], c = v2[d], e = v3[d];
            #pragma unroll
            for (int o = 0; o < 8; o++) {
                const float s = sp[o][d];
                acc[o][0] = fmaf(s, a,  acc[o][0]);
                acc[o][1] = fmaf(s, b2, acc[o][1]);
                acc[o][2] = fmaf(s, c,  acc[o][2]);
                acc[o][3] = fmaf(s, e,  acc[o][3]);
            }
        }
        #pragma unroll
        for (int o = 0; o < 8; o++)
            #pragma unroll
            for (int i = 0; i < 4; i++)
                attn_s[o][tid + 256 * i] = acc[o][i];
    }
    __syncthreads();

    {
        const int o = wid;
        float4 vals[8];
        #pragma unroll
        for (int j = 0; j < 8; j++)
            vals[j] = *(float4*)&attn_s[o][lane * 4 + 128 * j];
        float mx = -1e30f;
        #pragma unroll
        for (int j = 0; j < 8; j++)
            mx = fmaxf(mx, fmaxf(fmaxf(vals[j].x, vals[j].y), fmaxf(vals[j].z, vals[j].w)));
        mx = warp_max(mx);
        float sum = 0.0f;
        #pragma unroll
        for (int j = 0; j < 8; j++) {
            vals[j].x = expf(vals[j].x - mx);
            vals[j].y = expf(vals[j].y - mx);
            vals[j].z = expf(vals[j].z - mx);
            vals[j].w = expf(vals[j].w - mx);
            sum += vals[j].x + vals[j].y + vals[j].z + vals[j].w;
        }
        sum = warp_sum(sum);
        const float inv = 1.0f / sum;
        float ent = 0.0f;
        float* outA = out + ATT_OFF + (size_t)(row0 + o) * N_;
        #pragma unroll
        for (int j = 0; j < 8; j++) {
            vals[j].x *= inv; vals[j].y *= inv; vals[j].z *= inv; vals[j].w *= inv;
            *(float4*)&attn_s[o][lane * 4 + 128 * j] = vals[j];
            *(float4*)&outA[lane * 4 + 128 * j] = vals[j];
            ent += vals[j].x * logf(fmaxf(vals[j].x, 1e-8f));
            ent += vals[j].y * logf(fmaxf(vals[j].y, 1e-8f));
            ent += vals[j].z * logf(fmaxf(vals[j].z, 1e-8f));
            ent += vals[j].w * logf(fmaxf(vals[j].w, 1e-8f));
        }
        ent = warp_sum(ent);
        if (lane == 0) atomicAdd(&s_ent, ent);
    }
    __syncthreads();

    float ev[8];
    #pragma unroll
    for (int o = 0; o < 8; o++) ev[o] = 0.0f;
    {
        const float* vcol = g_visual + (size_t)b * N_ * D_ + tid;
        #pragma unroll 4
        for (int n = 0; n < N_; n++) {
            const float v = vcol[(size_t)n * D_];
            #pragma unroll
            for (int o = 0; o < 8; o++)
                ev[o] = fmaf(attn_s[o][n], v, ev[o]);
        }
    }

    #pragma unroll
    for (int o = 0; o < 8; o++)
        out[EV_OFF + (size_t)(row0 + o) * D_ + tid] = ev[o];

    const float lw = Wc[tid];
    const float bc = bcp[0];
    #pragma unroll
    for (int o = 0; o < 8; o++) {
        float v = warp_sum(ev[o] * lw);
        if (lane == 0) s_red[wid] = v;
        __syncthreads();
        if (tid == 0) {
            float s = 0.0f;
            #pragma unroll
            for (int w = 0; w < 8; w++) s += s_red[w];
            out[LOG_OFF + row0 + o] = s + bc;
        }
        __syncthreads();
    }

    float lsum = 0.0f;
    #pragma unroll
    for (int o = 0; o < 8; o++) {
        const int row = row0 + o;
        const float lab = labels[row];
        const float ph = g_phrase[(size_t)row * D_ + tid];
        const float df = ev[o] - lab * ph;
        lsum = fmaf(df, df, lsum);
    }
    lsum = warp_sum(lsum);
    if (lane == 0) s_red[wid] = lsum;
    __syncthreads();
    if (tid == 0) {
        float s = 0.0f;
        #pragma unroll
        for (int w = 0; w < 8; w++) s += s_red[w];
        atomicAdd(&g_accum[0], s);
        atomicAdd(&g_accum[1], s_ent);
    }
}

__global__ void k_finalize(float* __restrict__ out) {
    const float proto_loss = g_accum[0] / (float)(B_ * O_ * D_);
    const float sparse_loss = -g_accum[1] / (float)(B_ * O_);
    out[LOSS_OFF] = proto_loss + 0.01f * sparse_loss;
}

extern "C" void kernel_launch(void* const* d_in, const int* in_sizes, int n_in,
                              void* d_out, int out_size)
{
    (void)in_sizes; (void)n_in; (void)out_size;
    const float* visual_tokens = (const float*)d_in[0];
    const float* phrase_states = (const float*)d_in[1];
    const float* labels        = (const float*)d_in[2];
    const float* Wv            = (const float*)d_in[3];
    const float* bv            = (const float*)d_in[4];
    const float* Wp            = (const float*)d_in[5];
    const float* bp            = (const float*)d_in[6];
    const float* proto         = (const float*)d_in[7];
    const float* Wc            = (const float*)d_in[8];
    const float* bc            = (const float*)d_in[9];
    float* out = (float*)d_out;

    float* hv = nullptr;
    float* hp = nullptr;
    cudaGetSymbolAddress((void**)&hv, g_visual);
    cudaGetSymbolAddress((void**)&hp, g_phrase);

    k_zero<<<1, 1>>>();
    k_gemm_bias<<<dim3(D_ / BN, MV / BM), 256>>>(visual_tokens, Wv, bv, hv, MV, H_, D_);
    k_gemm_bias<<<dim3(D_ / BN, MP / BM), 256>>>(phrase_states, Wp, bp, hp, MP, H_, D_);
    k_norm_visual<<<MV / 8, 256>>>();
    k_phrase_proto<<<MP / 8, 256>>>(proto);
    k_attention<<<dim3(8, B_), 256>>>(labels, Wc, bc, out);
    k_finalize<<<1, 1>>>(out);
}

// round 5
// speedup vs baseline: 1.7625x; 1.7625x over previous
#include <cuda_runtime.h>
#include <cuda_bf16.h>
#include <cstdint>

#define B_  16
#define N_  1024
#define O_  64
#define H_  1024
#define D_  256

#define MV  (B_ * N_)      // 16384
#define MP  (B_ * O_)      // 1024

#define LOG_OFF  0
#define ATT_OFF  (B_ * O_)
#define EV_OFF   (ATT_OFF + B_ * O_ * N_)
#define LOSS_OFF (EV_OFF + B_ * O_ * D_)

// ---------------- device scratch ----------------
__device__ float g_visual[MV * D_];
__device__ float g_phrase[MP * D_];
__device__ float g_protoN[MP * D_];
__device__ float g_accum[2];

__device__ __align__(16) __nv_bfloat16 g_a_hi[MV * H_];
__device__ __align__(16) __nv_bfloat16 g_a_lo[MV * H_];
__device__ __align__(16) __nv_bfloat16 g_pa_hi[MP * H_];
__device__ __align__(16) __nv_bfloat16 g_pa_lo[MP * H_];
__device__ __align__(16) __nv_bfloat16 g_wv_hi[H_ * D_];   // row-major [K][N]
__device__ __align__(16) __nv_bfloat16 g_wv_lo[H_ * D_];
__device__ __align__(16) __nv_bfloat16 g_wp_hi[H_ * D_];
__device__ __align__(16) __nv_bfloat16 g_wp_lo[H_ * D_];

__global__ void k_zero() { g_accum[0] = 0.0f; g_accum[1] = 0.0f; }

// ---------------- helpers ----------------
__device__ __forceinline__ uint32_t smem_u32(const void* p) {
    uint32_t a;
    asm("{ .reg .u64 t; cvta.to.shared.u64 t, %1; cvt.u32.u64 %0, t; }" : "=r"(a) : "l"(p));
    return a;
}
__device__ __forceinline__ void cpa16(uint32_t s, const void* g) {
    asm volatile("cp.async.cg.shared.global [%0], [%1], 16;" :: "r"(s), "l"(g));
}
#define CP_COMMIT() asm volatile("cp.async.commit_group;" ::: "memory")
#define CP_WAIT1()  asm volatile("cp.async.wait_group 1;" ::: "memory")

__device__ __forceinline__ void ldm_x4(uint32_t* r, uint32_t a) {
    asm volatile("ldmatrix.sync.aligned.m8n8.x4.shared.b16 {%0,%1,%2,%3}, [%4];"
        : "=r"(r[0]), "=r"(r[1]), "=r"(r[2]), "=r"(r[3]) : "r"(a));
}
__device__ __forceinline__ void ldm_x4t(uint32_t* r, uint32_t a) {
    asm volatile("ldmatrix.sync.aligned.m8n8.x4.trans.shared.b16 {%0,%1,%2,%3}, [%4];"
        : "=r"(r[0]), "=r"(r[1]), "=r"(r[2]), "=r"(r[3]) : "r"(a));
}
__device__ __forceinline__ void mma16816(float* c, const uint32_t* a, const uint32_t* b) {
    asm volatile(
        "mma.sync.aligned.m16n8k16.row.col.f32.bf16.bf16.f32 "
        "{%0,%1,%2,%3}, {%4,%5,%6,%7}, {%8,%9}, {%0,%1,%2,%3};"
        : "+f"(c[0]), "+f"(c[1]), "+f"(c[2]), "+f"(c[3])
        : "r"(a[0]), "r"(a[1]), "r"(a[2]), "r"(a[3]), "r"(b[0]), "r"(b[1]));
}

__device__ __forceinline__ float warp_sum(float v) {
    #pragma unroll
    for (int o = 16; o > 0; o >>= 1) v += __shfl_xor_sync(0xffffffffu, v, o);
    return v;
}
__device__ __forceinline__ float warp_max(float v) {
    #pragma unroll
    for (int o = 16; o > 0; o >>= 1) v = fmaxf(v, __shfl_xor_sync(0xffffffffu, v, o));
    return v;
}

// ---------------- split conversion ----------------
__global__ __launch_bounds__(256) void k_split(const float* __restrict__ x,
                                               __nv_bfloat16* __restrict__ hi,
                                               __nv_bfloat16* __restrict__ lo, int n4)
{
    for (int i = blockIdx.x * blockDim.x + threadIdx.x; i < n4; i += gridDim.x * blockDim.x) {
        float4 v = ((const float4*)x)[i];
        __nv_bfloat16 h0 = __float2bfloat16(v.x), h1 = __float2bfloat16(v.y);
        __nv_bfloat16 h2 = __float2bfloat16(v.z), h3 = __float2bfloat16(v.w);
        __nv_bfloat162 H0; H0.x = h0; H0.y = h1;
        __nv_bfloat162 H1; H1.x = h2; H1.y = h3;
        ((__nv_bfloat162*)hi)[i * 2]     = H0;
        ((__nv_bfloat162*)hi)[i * 2 + 1] = H1;
        __nv_bfloat162 L0, L1;
        L0.x = __float2bfloat16(v.x - __bfloat162float(h0));
        L0.y = __float2bfloat16(v.y - __bfloat162float(h1));
        L1.x = __float2bfloat16(v.z - __bfloat162float(h2));
        L1.y = __float2bfloat16(v.w - __bfloat162float(h3));
        ((__nv_bfloat162*)lo)[i * 2]     = L0;
        ((__nv_bfloat162*)lo)[i * 2 + 1] = L1;
    }
}

// ---------------- mma.sync GEMM ----------------
// C[M,256] = A[M,1024] @ W[1024,256] + bias, 3-term bf16 split.
// BM=128 BN=64 BK=32, 256 threads = 8 warps (4m x 2n), warp tile 32x32.
#define NSTAGE (H_ / 32)          // 32 k-chunks
#define SMEM_STAGE 24576          // AH 8K | AL 8K | BH 4K | BL 4K
#define GEMM_SMEM (2 * SMEM_STAGE)

__global__ __launch_bounds__(256) void k_gemm_mma(const float* __restrict__ bv,
                                                  const float* __restrict__ bp)
{
    extern __shared__ char smem[];
    const uint32_t sb = smem_u32(smem);
    const int tid = threadIdx.x;
    const int lane = tid & 31;
    const int wid = tid >> 5;
    const int wm = wid & 3;            // 0..3
    const int wn = wid >> 2;           // 0..1
    const int n0 = blockIdx.x * 64;

    const bool isV = blockIdx.y < (MV / 128);
    const __nv_bfloat16 *Ah, *Al, *Bh, *Bl;
    const float* bias;
    float* C;
    int m0;
    if (isV) { Ah = g_a_hi;  Al = g_a_lo;  Bh = g_wv_hi; Bl = g_wv_lo; bias = bv; C = g_visual; m0 = blockIdx.y * 128; }
    else     { Ah = g_pa_hi; Al = g_pa_lo; Bh = g_wp_hi; Bl = g_wp_lo; bias = bp; C = g_phrase; m0 = (blockIdx.y - MV / 128) * 128; }

    // per-thread load coordinates
    const int a_r0 = tid >> 2;             // row for first A chunk (0..63)
    const int a_c  = tid & 3;              // 16B chunk within 64B A row
    const int b_r  = tid >> 3;             // 0..31
    const int b_c  = tid & 7;              // 16B chunk within 128B B row
    const uint32_t a_so0 = (uint32_t)(a_r0 * 64 + ((a_c ^ ((a_r0 >> 1) & 3)) << 4));
    const int a_r1 = a_r0 + 64;
    const uint32_t a_so1 = (uint32_t)(a_r1 * 64 + ((a_c ^ ((a_r1 >> 1) & 3)) << 4));
    const uint32_t b_so  = (uint32_t)(b_r * 128 + ((b_c ^ (b_r & 7)) << 4));

    float acc[2][4][4];
    #pragma unroll
    for (int i = 0; i < 2; i++)
        #pragma unroll
        for (int j = 0; j < 4; j++)
            #pragma unroll
            for (int k = 0; k < 4; k++) acc[i][j][k] = 0.0f;

    // prologue: stage 0
    {
        const int k0 = 0;
        const uint32_t st = sb;
        cpa16(st + a_so0,        Ah + (size_t)(m0 + a_r0) * H_ + k0 + a_c * 8);
        cpa16(st + a_so1,        Ah + (size_t)(m0 + a_r1) * H_ + k0 + a_c * 8);
        cpa16(st + 8192 + a_so0, Al + (size_t)(m0 + a_r0) * H_ + k0 + a_c * 8);
        cpa16(st + 8192 + a_so1, Al + (size_t)(m0 + a_r1) * H_ + k0 + a_c * 8);
        cpa16(st + 16384 + b_so, Bh + (size_t)(k0 + b_r) * D_ + n0 + b_c * 8);
        cpa16(st + 20480 + b_so, Bl + (size_t)(k0 + b_r) * D_ + n0 + b_c * 8);
    }
    CP_COMMIT();

    for (int s = 0; s < NSTAGE; s++) {
        if (s + 1 < NSTAGE) {
            const int k0 = (s + 1) * 32;
            const uint32_t st = sb + ((s + 1) & 1) * SMEM_STAGE;
            cpa16(st + a_so0,        Ah + (size_t)(m0 + a_r0) * H_ + k0 + a_c * 8);
            cpa16(st + a_so1,        Ah + (size_t)(m0 + a_r1) * H_ + k0 + a_c * 8);
            cpa16(st + 8192 + a_so0, Al + (size_t)(m0 + a_r0) * H_ + k0 + a_c * 8);
            cpa16(st + 8192 + a_so1, Al + (size_t)(m0 + a_r1) * H_ + k0 + a_c * 8);
            cpa16(st + 16384 + b_so, Bh + (size_t)(k0 + b_r) * D_ + n0 + b_c * 8);
            cpa16(st + 20480 + b_so, Bl + (size_t)(k0 + b_r) * D_ + n0 + b_c * 8);
        }
        CP_COMMIT();
        CP_WAIT1();
        __syncthreads();

        const uint32_t aBase = sb + (s & 1) * SMEM_STAGE;
        const uint32_t bBase = aBase + 16384;

        #pragma unroll
        for (int ks = 0; ks < 2; ks++) {
            uint32_t ahf[2][4], alf[2][4], bhf[4][2], blf[4][2];
            #pragma unroll
            for (int mf = 0; mf < 2; mf++) {
                const int row = wm * 32 + mf * 16 + ((lane >> 3) & 1) * 8 + (lane & 7);
                const int ch  = ks * 2 + (lane >> 4);
                const uint32_t addr = aBase + (uint32_t)(row * 64 + ((ch ^ ((row >> 1) & 3)) << 4));
                ldm_x4(ahf[mf], addr);
                ldm_x4(alf[mf], addr + 8192);
            }
            #pragma unroll
            for (int g = 0; g < 2; g++) {
                const int row = ks * 16 + ((lane >> 3) & 1) * 8 + (lane & 7);
                const int ch  = wn * 4 + g * 2 + (lane >> 4);
                const uint32_t addr = bBase + (uint32_t)(row * 128 + ((ch ^ (row & 7)) << 4));
                uint32_t t[4];
                ldm_x4t(t, addr);
                bhf[g * 2][0] = t[0]; bhf[g * 2][1] = t[1];
                bhf[g * 2 + 1][0] = t[2]; bhf[g * 2 + 1][1] = t[3];
                ldm_x4t(t, addr + 4096);
                blf[g * 2][0] = t[0]; blf[g * 2][1] = t[1];
                blf[g * 2 + 1][0] = t[2]; blf[g * 2 + 1][1] = t[3];
            }
            #pragma unroll
            for (int mf = 0; mf < 2; mf++)
                #pragma unroll
                for (int nf = 0; nf < 4; nf++) {
                    mma16816(acc[mf][nf], ahf[mf], bhf[nf]);
                    mma16816(acc[mf][nf], ahf[mf], blf[nf]);
                    mma16816(acc[mf][nf], alf[mf], bhf[nf]);
                }
        }
        __syncthreads();
    }

    // epilogue: add bias, write C
    #pragma unroll
    for (int mf = 0; mf < 2; mf++)
        #pragma unroll
        for (int nf = 0; nf < 4; nf++) {
            const int m = m0 + wm * 32 + mf * 16 + (lane >> 2);
            const int n = n0 + wn * 32 + nf * 8 + (lane & 3) * 2;
            const float bx = bias[n], by = bias[n + 1];
            float2 r0; r0.x = acc[mf][nf][0] + bx; r0.y = acc[mf][nf][1] + by;
            float2 r1; r1.x = acc[mf][nf][2] + bx; r1.y = acc[mf][nf][3] + by;
            *(float2*)&C[(size_t)m * D_ + n]       = r0;
            *(float2*)&C[(size_t)(m + 8) * D_ + n] = r1;
        }
}

// ---------------- normalize ----------------
__global__ __launch_bounds__(256) void k_norm_visual() {
    const int wid = threadIdx.x / 32;
    const int lane = threadIdx.x % 32;
    const int row = blockIdx.x * 8 + wid;
    float* p = g_visual + (size_t)row * D_;

    float4 x0 = *(float4*)&p[lane * 4];
    float4 x1 = *(float4*)&p[128 + lane * 4];
    float s = x0.x * x0.x + x0.y * x0.y + x0.z * x0.z + x0.w * x0.w
            + x1.x * x1.x + x1.y * x1.y + x1.z * x1.z + x1.w * x1.w;
    s = warp_sum(s);
    const float inv = 1.0f / fmaxf(sqrtf(s), 1e-12f);
    x0.x *= inv; x0.y *= inv; x0.z *= inv; x0.w *= inv;
    x1.x *= inv; x1.y *= inv; x1.z *= inv; x1.w *= inv;
    *(float4*)&p[lane * 4] = x0;
    *(float4*)&p[128 + lane * 4] = x1;
}

__global__ __launch_bounds__(256) void k_phrase_proto(const float* __restrict__ proto) {
    const int wid = threadIdx.x / 32;
    const int lane = threadIdx.x % 32;
    const int row = blockIdx.x * 8 + wid;
    const int o = row % O_;
    float* pp = g_phrase + (size_t)row * D_;

    float4 x0 = *(float4*)&pp[lane * 4];
    float4 x1 = *(float4*)&pp[128 + lane * 4];
    float s = x0.x * x0.x + x0.y * x0.y + x0.z * x0.z + x0.w * x0.w
            + x1.x * x1.x + x1.y * x1.y + x1.z * x1.z + x1.w * x1.w;
    s = warp_sum(s);
    const float inv = 1.0f / fmaxf(sqrtf(s), 1e-12f);
    x0.x *= inv; x0.y *= inv; x0.z *= inv; x0.w *= inv;
    x1.x *= inv; x1.y *= inv; x1.z *= inv; x1.w *= inv;
    *(float4*)&pp[lane * 4] = x0;
    *(float4*)&pp[128 + lane * 4] = x1;

    const float4 q0g = *(const float4*)&proto[(size_t)o * D_ + lane * 4];
    const float4 q1g = *(const float4*)&proto[(size_t)o * D_ + 128 + lane * 4];
    float4 q0, q1;
    q0.x = q0g.x + x0.x; q0.y = q0g.y + x0.y; q0.z = q0g.z + x0.z; q0.w = q0g.w + x0.w;
    q1.x = q1g.x + x1.x; q1.y = q1g.y + x1.y; q1.z = q1g.z + x1.z; q1.w = q1g.w + x1.w;
    float s2 = q0.x * q0.x + q0.y * q0.y + q0.z * q0.z + q0.w * q0.w
             + q1.x * q1.x + q1.y * q1.y + q1.z * q1.z + q1.w * q1.w;
    s2 = warp_sum(s2);
    const float inv2 = 1.0f / fmaxf(sqrtf(s2), 1e-12f);
    q0.x *= inv2; q0.y *= inv2; q0.z *= inv2; q0.w *= inv2;
    q1.x *= inv2; q1.y *= inv2; q1.z *= inv2; q1.w *= inv2;
    float* pn = g_protoN + (size_t)row * D_;
    *(float4*)&pn[lane * 4] = q0;
    *(float4*)&pn[128 + lane * 4] = q1;
}

// ---------------- fused attention ----------------
__global__ __launch_bounds__(256) void k_attention(
    const float* __restrict__ labels, const float* __restrict__ Wc,
    const float* __restrict__ bcp, float* __restrict__ out)
{
    __shared__ float sp[8][D_];
    __shared__ float attn_s[8][N_];
    __shared__ float s_red[8];
    __shared__ float s_ent;

    const int tid = threadIdx.x;
    const int og = blockIdx.x;
    const int b  = blockIdx.y;
    const int wid = tid / 32, lane = tid % 32;
    const int row0 = b * O_ + og * 8;

    #pragma unroll
    for (int i = 0; i < 8; i++)
        sp[i][tid] = g_protoN[(size_t)(row0 + i) * D_ + tid];
    if (tid == 0) s_ent = 0.0f;
    __syncthreads();

    {
        const float* v0 = g_visual + ((size_t)(b * N_ + tid)) * D_;
        const float* v1 = v0 + 256 * D_;
        const float* v2 = v1 + 256 * D_;
        const float* v3 = v2 + 256 * D_;
        float acc[8][4];
        #pragma unroll
        for (int o = 0; o < 8; o++)
            #pragma unroll
            for (int i = 0; i < 4; i++) acc[o][i] = 0.0f;

        #pragma unroll 4
        for (int d = 0; d < D_; d++) {
            const float a = v0[d], b2 = v1[d], c = v2[d], e = v3[d];
            #pragma unroll
            for (int o = 0; o < 8; o++) {
                const float s = sp[o][d];
                acc[o][0] = fmaf(s, a,  acc[o][0]);
                acc[o][1] = fmaf(s, b2, acc[o][1]);
                acc[o][2] = fmaf(s, c,  acc[o][2]);
                acc[o][3] = fmaf(s, e,  acc[o][3]);
            }
        }
        #pragma unroll
        for (int o = 0; o < 8; o++)
            #pragma unroll
            for (int i = 0; i < 4; i++)
                attn_s[o][tid + 256 * i] = acc[o][i];
    }
    __syncthreads();

    {
        const int o = wid;
        float4 vals[8];
        #pragma unroll
        for (int j = 0; j < 8; j++)
            vals[j] = *(float4*)&attn_s[o][lane * 4 + 128 * j];
        float mx = -1e30f;
        #pragma unroll
        for (int j = 0; j < 8; j++)
            mx = fmaxf(mx, fmaxf(fmaxf(vals[j].x, vals[j].y), fmaxf(vals[j].z, vals[j].w)));
        mx = warp_max(mx);
        float sum = 0.0f;
        #pragma unroll
        for (int j = 0; j < 8; j++) {
            vals[j].x = expf(vals[j].x - mx);
            vals[j].y = expf(vals[j].y - mx);
            vals[j].z = expf(vals[j].z - mx);
            vals[j].w = expf(vals[j].w - mx);
            sum += vals[j].x + vals[j].y + vals[j].z + vals[j].w;
        }
        sum = warp_sum(sum);
        const float inv = 1.0f / sum;
        float ent = 0.0f;
        float* outA = out + ATT_OFF + (size_t)(row0 + o) * N_;
        #pragma unroll
        for (int j = 0; j < 8; j++) {
            vals[j].x *= inv; vals[j].y *= inv; vals[j].z *= inv; vals[j].w *= inv;
            *(float4*)&attn_s[o][lane * 4 + 128 * j] = vals[j];
            *(float4*)&outA[lane * 4 + 128 * j] = vals[j];
            ent += vals[j].x * logf(fmaxf(vals[j].x, 1e-8f));
            ent += vals[j].y * logf(fmaxf(vals[j].y, 1e-8f));
            ent += vals[j].z * logf(fmaxf(vals[j].z, 1e-8f));
            ent += vals[j].w * logf(fmaxf(vals[j].w, 1e-8f));
        }
        ent = warp_sum(ent);
        if (lane == 0) atomicAdd(&s_ent, ent);
    }
    __syncthreads();

    float ev[8];
    #pragma unroll
    for (int o = 0; o < 8; o++) ev[o] = 0.0f;
    {
        const float* vcol = g_visual + (size_t)b * N_ * D_ + tid;
        #pragma unroll 4
        for (int n = 0; n < N_; n++) {
            const float v = vcol[(size_t)n * D_];
            #pragma unroll
            for (int o = 0; o < 8; o++)
                ev[o] = fmaf(attn_s[o][n], v, ev[o]);
        }
    }

    #pragma unroll
    for (int o = 0; o < 8; o++)
        out[EV_OFF + (size_t)(row0 + o) * D_ + tid] = ev[o];

    const float lw = Wc[tid];
    const float bc = bcp[0];
    #pragma unroll
    for (int o = 0; o < 8; o++) {
        float v = warp_sum(ev[o] * lw);
        if (lane == 0) s_red[wid] = v;
        __syncthreads();
        if (tid == 0) {
            float s = 0.0f;
            #pragma unroll
            for (int w = 0; w < 8; w++) s += s_red[w];
            out[LOG_OFF + row0 + o] = s + bc;
        }
        __syncthreads();
    }

    float lsum = 0.0f;
    #pragma unroll
    for (int o = 0; o < 8; o++) {
        const int row = row0 + o;
        const float lab = labels[row];
        const float ph = g_phrase[(size_t)row * D_ + tid];
        const float df = ev[o] - lab * ph;
        lsum = fmaf(df, df, lsum);
    }
    lsum = warp_sum(lsum);
    if (lane == 0) s_red[wid] = lsum;
    __syncthreads();
    if (tid == 0) {
        float s = 0.0f;
        #pragma unroll
        for (int w = 0; w < 8; w++) s += s_red[w];
        atomicAdd(&g_accum[0], s);
        atomicAdd(&g_accum[1], s_ent);
    }
}

__global__ void k_finalize(float* __restrict__ out) {
    const float proto_loss = g_accum[0] / (float)(B_ * O_ * D_);
    const float sparse_loss = -g_accum[1] / (float)(B_ * O_);
    out[LOSS_OFF] = proto_loss + 0.01f * sparse_loss;
}

// ---------------- launch ----------------
extern "C" void kernel_launch(void* const* d_in, const int* in_sizes, int n_in,
                              void* d_out, int out_size)
{
    (void)in_sizes; (void)n_in; (void)out_size;
    const float* visual_tokens = (const float*)d_in[0];
    const float* phrase_states = (const float*)d_in[1];
    const float* labels        = (const float*)d_in[2];
    const float* Wv            = (const float*)d_in[3];
    const float* bv            = (const float*)d_in[4];
    const float* Wp            = (const float*)d_in[5];
    const float* bp            = (const float*)d_in[6];
    const float* proto         = (const float*)d_in[7];
    const float* Wc            = (const float*)d_in[8];
    const float* bc            = (const float*)d_in[9];
    float* out = (float*)d_out;

    __nv_bfloat16 *ah, *al, *pah, *pal, *wvh, *wvl, *wph, *wpl;
    cudaGetSymbolAddress((void**)&ah,  g_a_hi);
    cudaGetSymbolAddress((void**)&al,  g_a_lo);
    cudaGetSymbolAddress((void**)&pah, g_pa_hi);
    cudaGetSymbolAddress((void**)&pal, g_pa_lo);
    cudaGetSymbolAddress((void**)&wvh, g_wv_hi);
    cudaGetSymbolAddress((void**)&wvl, g_wv_lo);
    cudaGetSymbolAddress((void**)&wph, g_wp_hi);
    cudaGetSymbolAddress((void**)&wpl, g_wp_lo);

    cudaFuncSetAttribute(k_gemm_mma, cudaFuncAttributeMaxDynamicSharedMemorySize, GEMM_SMEM);

    k_zero<<<1, 1>>>();
    k_split<<<4096, 256>>>(visual_tokens, ah, al, MV * H_ / 4);
    k_split<<<1024, 256>>>(phrase_states, pah, pal, MP * H_ / 4);
    k_split<<<256, 256>>>(Wv, wvh, wvl, H_ * D_ / 4);
    k_split<<<256, 256>>>(Wp, wph, wpl, H_ * D_ / 4);
    k_gemm_mma<<<dim3(D_ / 64, MV / 128 + MP / 128), 256, GEMM_SMEM>>>(bv, bp);
    k_norm_visual<<<MV / 8, 256>>>();
    k_phrase_proto<<<MP / 8, 256>>>(proto);
    k_attention<<<dim3(8, B_), 256>>>(labels, Wc, bc, out);
    k_finalize<<<1, 1>>>(out);
}

// round 6
// speedup vs baseline: 1.7971x; 1.0196x over previous
#include <cuda_runtime.h>
#include <cuda_bf16.h>
#include <cstdint>

#define B_  16
#define N_  1024
#define O_  64
#define H_  1024
#define D_  256

#define MV  (B_ * N_)      // 16384
#define MP  (B_ * O_)      // 1024

#define LOG_OFF  0
#define ATT_OFF  (B_ * O_)
#define EV_OFF   (ATT_OFF + B_ * O_ * N_)
#define LOSS_OFF (EV_OFF + B_ * O_ * D_)

// ---------------- device scratch ----------------
__device__ float g_visual[MV * D_];   // normalized visual (GEMM epilogue)
__device__ float g_phrase[MP * D_];   // normalized phrase (GEMM epilogue)
__device__ float g_protoN[MP * D_];
__device__ float g_accum[2];

__device__ __align__(16) __nv_bfloat16 g_a_hi[MV * H_];
__device__ __align__(16) __nv_bfloat16 g_a_lo[MV * H_];
__device__ __align__(16) __nv_bfloat16 g_pa_hi[MP * H_];
__device__ __align__(16) __nv_bfloat16 g_pa_lo[MP * H_];
__device__ __align__(16) __nv_bfloat16 g_wv_hi[H_ * D_];   // row-major [K][N]
__device__ __align__(16) __nv_bfloat16 g_wv_lo[H_ * D_];
__device__ __align__(16) __nv_bfloat16 g_wp_hi[H_ * D_];
__device__ __align__(16) __nv_bfloat16 g_wp_lo[H_ * D_];

__global__ void k_zero() { g_accum[0] = 0.0f; g_accum[1] = 0.0f; }

// ---------------- helpers ----------------
__device__ __forceinline__ uint32_t smem_u32(const void* p) {
    uint32_t a;
    asm("{ .reg .u64 t; cvta.to.shared.u64 t, %1; cvt.u32.u64 %0, t; }" : "=r"(a) : "l"(p));
    return a;
}
__device__ __forceinline__ void cpa16(uint32_t s, const void* g) {
    asm volatile("cp.async.cg.shared.global [%0], [%1], 16;" :: "r"(s), "l"(g));
}
#define CP_COMMIT() asm volatile("cp.async.commit_group;" ::: "memory")
#define CP_WAIT1()  asm volatile("cp.async.wait_group 1;" ::: "memory")

__device__ __forceinline__ void ldm_x4(uint32_t* r, uint32_t a) {
    asm volatile("ldmatrix.sync.aligned.m8n8.x4.shared.b16 {%0,%1,%2,%3}, [%4];"
        : "=r"(r[0]), "=r"(r[1]), "=r"(r[2]), "=r"(r[3]) : "r"(a));
}
__device__ __forceinline__ void ldm_x4t(uint32_t* r, uint32_t a) {
    asm volatile("ldmatrix.sync.aligned.m8n8.x4.trans.shared.b16 {%0,%1,%2,%3}, [%4];"
        : "=r"(r[0]), "=r"(r[1]), "=r"(r[2]), "=r"(r[3]) : "r"(a));
}
__device__ __forceinline__ void mma16816(float* c, const uint32_t* a, const uint32_t* b) {
    asm volatile(
        "mma.sync.aligned.m16n8k16.row.col.f32.bf16.bf16.f32 "
        "{%0,%1,%2,%3}, {%4,%5,%6,%7}, {%8,%9}, {%0,%1,%2,%3};"
        : "+f"(c[0]), "+f"(c[1]), "+f"(c[2]), "+f"(c[3])
        : "r"(a[0]), "r"(a[1]), "r"(a[2]), "r"(a[3]), "r"(b[0]), "r"(b[1]));
}

__device__ __forceinline__ float warp_sum(float v) {
    #pragma unroll
    for (int o = 16; o > 0; o >>= 1) v += __shfl_xor_sync(0xffffffffu, v, o);
    return v;
}
__device__ __forceinline__ float warp_max(float v) {
    #pragma unroll
    for (int o = 16; o > 0; o >>= 1) v = fmaxf(v, __shfl_xor_sync(0xffffffffu, v, o));
    return v;
}

// ---------------- split conversion ----------------
__global__ __launch_bounds__(256) void k_split(const float* __restrict__ x,
                                               __nv_bfloat16* __restrict__ hi,
                                               __nv_bfloat16* __restrict__ lo, int n4)
{
    for (int i = blockIdx.x * blockDim.x + threadIdx.x; i < n4; i += gridDim.x * blockDim.x) {
        float4 v = ((const float4*)x)[i];
        __nv_bfloat16 h0 = __float2bfloat16(v.x), h1 = __float2bfloat16(v.y);
        __nv_bfloat16 h2 = __float2bfloat16(v.z), h3 = __float2bfloat16(v.w);
        __nv_bfloat162 H0; H0.x = h0; H0.y = h1;
        __nv_bfloat162 H1; H1.x = h2; H1.y = h3;
        ((__nv_bfloat162*)hi)[i * 2]     = H0;
        ((__nv_bfloat162*)hi)[i * 2 + 1] = H1;
        __nv_bfloat162 L0, L1;
        L0.x = __float2bfloat16(v.x - __bfloat162float(h0));
        L0.y = __float2bfloat16(v.y - __bfloat162float(h1));
        L1.x = __float2bfloat16(v.z - __bfloat162float(h2));
        L1.y = __float2bfloat16(v.w - __bfloat162float(h3));
        ((__nv_bfloat162*)lo)[i * 2]     = L0;
        ((__nv_bfloat162*)lo)[i * 2 + 1] = L1;
    }
}

// ---------------- mma.sync GEMM, BM=128 BN=256(full D) BK=32 ----------------
// 512 threads = 16 warps (4m x 4n), warp tile 32x64.
// Epilogue: bias add + row L2-normalize fused (CTA owns full rows).
#define NSTAGE (H_ / 32)
#define ST_AH 0
#define ST_AL 8192
#define ST_BH 16384
#define ST_BL 32768
#define SMEM_STAGE 49152
#define GEMM_SMEM (2 * SMEM_STAGE)

__global__ __launch_bounds__(512, 1) void k_gemm_mma(const float* __restrict__ bv,
                                                     const float* __restrict__ bp)
{
    extern __shared__ char smem[];
    const uint32_t sb = smem_u32(smem);
    const int tid = threadIdx.x;
    const int lane = tid & 31;
    const int wid = tid >> 5;          // 0..15
    const int wm = wid & 3;            // 0..3
    const int wn = wid >> 2;           // 0..3

    const bool isV = blockIdx.x < (MV / 128);
    const __nv_bfloat16 *Ah, *Al, *Bh, *Bl;
    const float* bias;
    float* C;
    int m0;
    if (isV) { Ah = g_a_hi;  Al = g_a_lo;  Bh = g_wv_hi; Bl = g_wv_lo; bias = bv; C = g_visual; m0 = blockIdx.x * 128; }
    else     { Ah = g_pa_hi; Al = g_pa_lo; Bh = g_wp_hi; Bl = g_wp_lo; bias = bp; C = g_phrase; m0 = (blockIdx.x - MV / 128) * 128; }

    // load coords: A = 128 rows x 4 chunks (16B) per hi/lo; B = 32 rows x 32 chunks per hi/lo
    const int a_r = tid >> 2;              // 0..127
    const int a_c = tid & 3;
    const uint32_t a_so = (uint32_t)(a_r * 64 + ((a_c ^ ((a_r >> 1) & 3)) << 4));
    const int b_r = tid >> 4;              // 0..31
    const int b_c = tid & 15;
    const uint32_t b_so0 = (uint32_t)(b_r * 512 + ((b_c ^ (b_r & 7)) << 4));
    const uint32_t b_so1 = (uint32_t)(b_r * 512 + (((b_c + 16) ^ (b_r & 7)) << 4));

    float acc[2][8][4];
    #pragma unroll
    for (int i = 0; i < 2; i++)
        #pragma unroll
        for (int j = 0; j < 8; j++)
            #pragma unroll
            for (int k = 0; k < 4; k++) acc[i][j][k] = 0.0f;

    // prologue
    {
        const uint32_t st = sb;
        cpa16(st + ST_AH + a_so, Ah + (size_t)(m0 + a_r) * H_ + a_c * 8);
        cpa16(st + ST_AL + a_so, Al + (size_t)(m0 + a_r) * H_ + a_c * 8);
        cpa16(st + ST_BH + b_so0, Bh + (size_t)b_r * D_ + b_c * 8);
        cpa16(st + ST_BH + b_so1, Bh + (size_t)b_r * D_ + (b_c + 16) * 8);
        cpa16(st + ST_BL + b_so0, Bl + (size_t)b_r * D_ + b_c * 8);
        cpa16(st + ST_BL + b_so1, Bl + (size_t)b_r * D_ + (b_c + 16) * 8);
    }
    CP_COMMIT();

    for (int s = 0; s < NSTAGE; s++) {
        if (s + 1 < NSTAGE) {
            const int k0 = (s + 1) * 32;
            const uint32_t st = sb + ((s + 1) & 1) * SMEM_STAGE;
            cpa16(st + ST_AH + a_so, Ah + (size_t)(m0 + a_r) * H_ + k0 + a_c * 8);
            cpa16(st + ST_AL + a_so, Al + (size_t)(m0 + a_r) * H_ + k0 + a_c * 8);
            cpa16(st + ST_BH + b_so0, Bh + (size_t)(k0 + b_r) * D_ + b_c * 8);
            cpa16(st + ST_BH + b_so1, Bh + (size_t)(k0 + b_r) * D_ + (b_c + 16) * 8);
            cpa16(st + ST_BL + b_so0, Bl + (size_t)(k0 + b_r) * D_ + b_c * 8);
            cpa16(st + ST_BL + b_so1, Bl + (size_t)(k0 + b_r) * D_ + (b_c + 16) * 8);
        }
        CP_COMMIT();
        CP_WAIT1();
        __syncthreads();

        const uint32_t base = sb + (s & 1) * SMEM_STAGE;

        #pragma unroll
        for (int ks = 0; ks < 2; ks++) {
            uint32_t ahf[2][4], alf[2][4];
            #pragma unroll
            for (int mf = 0; mf < 2; mf++) {
                const int row = wm * 32 + mf * 16 + ((lane >> 3) & 1) * 8 + (lane & 7);
                const int ch  = ks * 2 + (lane >> 4);
                const uint32_t addr = base + ST_AH + (uint32_t)(row * 64 + ((ch ^ ((row >> 1) & 3)) << 4));
                ldm_x4(ahf[mf], addr);
                ldm_x4(alf[mf], addr + (ST_AL - ST_AH));
            }
            #pragma unroll
            for (int g = 0; g < 4; g++) {
                const int row = ks * 16 + ((lane >> 3) & 1) * 8 + (lane & 7);
                const int ch  = wn * 8 + g * 2 + (lane >> 4);
                const uint32_t addr = base + ST_BH + (uint32_t)(row * 512 + ((ch ^ (row & 7)) << 4));
                uint32_t th[4], tl[4];
                ldm_x4t(th, addr);
                ldm_x4t(tl, addr + (ST_BL - ST_BH));
                uint32_t bh0[2] = {th[0], th[1]}, bh1[2] = {th[2], th[3]};
                uint32_t bl0[2] = {tl[0], tl[1]}, bl1[2] = {tl[2], tl[3]};
                #pragma unroll
                for (int mf = 0; mf < 2; mf++) {
                    mma16816(acc[mf][g * 2],     ahf[mf], bh0);
                    mma16816(acc[mf][g * 2],     ahf[mf], bl0);
                    mma16816(acc[mf][g * 2],     alf[mf], bh0);
                    mma16816(acc[mf][g * 2 + 1], ahf[mf], bh1);
                    mma16816(acc[mf][g * 2 + 1], ahf[mf], bl1);
                    mma16816(acc[mf][g * 2 + 1], alf[mf], bh1);
                }
            }
        }
        __syncthreads();
    }

    // ---- epilogue: bias + fused L2 row-normalize + store ----
    // add bias
    #pragma unroll
    for (int mf = 0; mf < 2; mf++)
        #pragma unroll
        for (int nf = 0; nf < 8; nf++) {
            const int n = wn * 64 + nf * 8 + (lane & 3) * 2;
            const float bx = bias[n], by = bias[n + 1];
            acc[mf][nf][0] += bx; acc[mf][nf][1] += by;
            acc[mf][nf][2] += bx; acc[mf][nf][3] += by;
        }

    float* part = (float*)smem;   // [4][128] per-wn row partial sq-sums
    #pragma unroll
    for (int mf = 0; mf < 2; mf++) {
        float p0 = 0.0f, p1 = 0.0f;
        #pragma unroll
        for (int nf = 0; nf < 8; nf++) {
            p0 = fmaf(acc[mf][nf][0], acc[mf][nf][0], p0);
            p0 = fmaf(acc[mf][nf][1], acc[mf][nf][1], p0);
            p1 = fmaf(acc[mf][nf][2], acc[mf][nf][2], p1);
            p1 = fmaf(acc[mf][nf][3], acc[mf][nf][3], p1);
        }
        p0 += __shfl_xor_sync(0xffffffffu, p0, 1);
        p0 += __shfl_xor_sync(0xffffffffu, p0, 2);
        p1 += __shfl_xor_sync(0xffffffffu, p1, 1);
        p1 += __shfl_xor_sync(0xffffffffu, p1, 2);
        if ((lane & 3) == 0) {
            const int r = wm * 32 + mf * 16 + (lane >> 2);
            part[wn * 128 + r]     = p0;
            part[wn * 128 + r + 8] = p1;
        }
    }
    __syncthreads();

    #pragma unroll
    for (int mf = 0; mf < 2; mf++) {
        const int r0 = wm * 32 + mf * 16 + (lane >> 2);
        const int r1 = r0 + 8;
        const float s0 = part[r0] + part[128 + r0] + part[256 + r0] + part[384 + r0];
        const float s1 = part[r1] + part[128 + r1] + part[256 + r1] + part[384 + r1];
        const float inv0 = 1.0f / fmaxf(sqrtf(s0), 1e-12f);
        const float inv1 = 1.0f / fmaxf(sqrtf(s1), 1e-12f);
        #pragma unroll
        for (int nf = 0; nf < 8; nf++) {
            const int n = wn * 64 + nf * 8 + (lane & 3) * 2;
            float2 w0; w0.x = acc[mf][nf][0] * inv0; w0.y = acc[mf][nf][1] * inv0;
            float2 w1; w1.x = acc[mf][nf][2] * inv1; w1.y = acc[mf][nf][3] * inv1;
            *(float2*)&C[(size_t)(m0 + r0) * D_ + n] = w0;
            *(float2*)&C[(size_t)(m0 + r1) * D_ + n] = w1;
        }
    }
}

// ---------------- prototypes = l2norm(proto + phrase_normalized) ----------------
__global__ __launch_bounds__(256) void k_phrase_proto(const float* __restrict__ proto) {
    const int wid = threadIdx.x / 32;
    const int lane = threadIdx.x % 32;
    const int row = blockIdx.x * 8 + wid;
    const int o = row % O_;
    const float* pp = g_phrase + (size_t)row * D_;

    float4 x0 = *(const float4*)&pp[lane * 4];
    float4 x1 = *(const float4*)&pp[128 + lane * 4];
    const float4 q0g = *(const float4*)&proto[(size_t)o * D_ + lane * 4];
    const float4 q1g = *(const float4*)&proto[(size_t)o * D_ + 128 + lane * 4];
    float4 q0, q1;
    q0.x = q0g.x + x0.x; q0.y = q0g.y + x0.y; q0.z = q0g.z + x0.z; q0.w = q0g.w + x0.w;
    q1.x = q1g.x + x1.x; q1.y = q1g.y + x1.y; q1.z = q1g.z + x1.z; q1.w = q1g.w + x1.w;
    float s2 = q0.x * q0.x + q0.y * q0.y + q0.z * q0.z + q0.w * q0.w
             + q1.x * q1.x + q1.y * q1.y + q1.z * q1.z + q1.w * q1.w;
    s2 = warp_sum(s2);
    const float inv2 = 1.0f / fmaxf(sqrtf(s2), 1e-12f);
    q0.x *= inv2; q0.y *= inv2; q0.z *= inv2; q0.w *= inv2;
    q1.x *= inv2; q1.y *= inv2; q1.z *= inv2; q1.w *= inv2;
    float* pn = g_protoN + (size_t)row * D_;
    *(float4*)&pn[lane * 4] = q0;
    *(float4*)&pn[128 + lane * 4] = q1;
}

// ---------------- fused attention ----------------
__global__ __launch_bounds__(256) void k_attention(
    const float* __restrict__ labels, const float* __restrict__ Wc,
    const float* __restrict__ bcp, float* __restrict__ out)
{
    __shared__ float sp[8][D_];
    __shared__ float attn_s[8][N_];
    __shared__ float s_red[8];
    __shared__ float s_ent;

    const int tid = threadIdx.x;
    const int og = blockIdx.x;
    const int b  = blockIdx.y;
    const int wid = tid / 32, lane = tid % 32;
    const int row0 = b * O_ + og * 8;

    #pragma unroll
    for (int i = 0; i < 8; i++)
        sp[i][tid] = g_protoN[(size_t)(row0 + i) * D_ + tid];
    if (tid == 0) s_ent = 0.0f;
    __syncthreads();

    {
        const float* v0 = g_visual + ((size_t)(b * N_ + tid)) * D_;
        const float* v1 = v0 + 256 * D_;
        const float* v2 = v1 + 256 * D_;
        const float* v3 = v2 + 256 * D_;
        float acc[8][4];
        #pragma unroll
        for (int o = 0; o < 8; o++)
            #pragma unroll
            for (int i = 0; i < 4; i++) acc[o][i] = 0.0f;

        #pragma unroll 4
        for (int d = 0; d < D_; d++) {
            const float a = v0[d], b2 = v1[d], c = v2[d], e = v3[d];
            #pragma unroll
            for (int o = 0; o < 8; o++) {
                const float s = sp[o][d];
                acc[o][0] = fmaf(s, a,  acc[o][0]);
                acc[o][1] = fmaf(s, b2, acc[o][1]);
                acc[o][2] = fmaf(s, c,  acc[o][2]);
                acc[o][3] = fmaf(s, e,  acc[o][3]);
            }
        }
        #pragma unroll
        for (int o = 0; o < 8; o++)
            #pragma unroll
            for (int i = 0; i < 4; i++)
                attn_s[o][tid + 256 * i] = acc[o][i];
    }
    __syncthreads();

    {
        const int o = wid;
        float4 vals[8];
        #pragma unroll
        for (int j = 0; j < 8; j++)
            vals[j] = *(float4*)&attn_s[o][lane * 4 + 128 * j];
        float mx = -1e30f;
        #pragma unroll
        for (int j = 0; j < 8; j++)
            mx = fmaxf(mx, fmaxf(fmaxf(vals[j].x, vals[j].y), fmaxf(vals[j].z, vals[j].w)));
        mx = warp_max(mx);
        float sum = 0.0f;
        #pragma unroll
        for (int j = 0; j < 8; j++) {
            vals[j].x = expf(vals[j].x - mx);
            vals[j].y = expf(vals[j].y - mx);
            vals[j].z = expf(vals[j].z - mx);
            vals[j].w = expf(vals[j].w - mx);
            sum += vals[j].x + vals[j].y + vals[j].z + vals[j].w;
        }
        sum = warp_sum(sum);
        const float inv = 1.0f / sum;
        float ent = 0.0f;
        float* outA = out + ATT_OFF + (size_t)(row0 + o) * N_;
        #pragma unroll
        for (int j = 0; j < 8; j++) {
            vals[j].x *= inv; vals[j].y *= inv; vals[j].z *= inv; vals[j].w *= inv;
            *(float4*)&attn_s[o][lane * 4 + 128 * j] = vals[j];
            *(float4*)&outA[lane * 4 + 128 * j] = vals[j];
            ent += vals[j].x * logf(fmaxf(vals[j].x, 1e-8f));
            ent += vals[j].y * logf(fmaxf(vals[j].y, 1e-8f));
            ent += vals[j].z * logf(fmaxf(vals[j].z, 1e-8f));
            ent += vals[j].w * logf(fmaxf(vals[j].w, 1e-8f));
        }
        ent = warp_sum(ent);
        if (lane == 0) atomicAdd(&s_ent, ent);
    }
    __syncthreads();

    float ev[8];
    #pragma unroll
    for (int o = 0; o < 8; o++) ev[o] = 0.0f;
    {
        const float* vcol = g_visual + (size_t)b * N_ * D_ + tid;
        #pragma unroll 4
        for (int n = 0; n < N_; n++) {
            const float v = vcol[(size_t)n * D_];
            #pragma unroll
            for (int o = 0; o < 8; o++)
                ev[o] = fmaf(attn_s[o][n], v, ev[o]);
        }
    }

    #pragma unroll
    for (int o = 0; o < 8; o++)
        out[EV_OFF + (size_t)(row0 + o) * D_ + tid] = ev[o];

    const float lw = Wc[tid];
    const float bc = bcp[0];
    #pragma unroll
    for (int o = 0; o < 8; o++) {
        float v = warp_sum(ev[o] * lw);
        if (lane == 0) s_red[wid] = v;
        __syncthreads();
        if (tid == 0) {
            float s = 0.0f;
            #pragma unroll
            for (int w = 0; w < 8; w++) s += s_red[w];
            out[LOG_OFF + row0 + o] = s + bc;
        }
        __syncthreads();
    }

    float lsum = 0.0f;
    #pragma unroll
    for (int o = 0; o < 8; o++) {
        const int row = row0 + o;
        const float lab = labels[row];
        const float ph = g_phrase[(size_t)row * D_ + tid];
        const float df = ev[o] - lab * ph;
        lsum = fmaf(df, df, lsum);
    }
    lsum = warp_sum(lsum);
    if (lane == 0) s_red[wid] = lsum;
    __syncthreads();
    if (tid == 0) {
        float s = 0.0f;
        #pragma unroll
        for (int w = 0; w < 8; w++) s += s_red[w];
        atomicAdd(&g_accum[0], s);
        atomicAdd(&g_accum[1], s_ent);
    }
}

__global__ void k_finalize(float* __restrict__ out) {
    const float proto_loss = g_accum[0] / (float)(B_ * O_ * D_);
    const float sparse_loss = -g_accum[1] / (float)(B_ * O_);
    out[LOSS_OFF] = proto_loss + 0.01f * sparse_loss;
}

// ---------------- launch ----------------
extern "C" void kernel_launch(void* const* d_in, const int* in_sizes, int n_in,
                              void* d_out, int out_size)
{
    (void)in_sizes; (void)n_in; (void)out_size;
    const float* visual_tokens = (const float*)d_in[0];
    const float* phrase_states = (const float*)d_in[1];
    const float* labels        = (const float*)d_in[2];
    const float* Wv            = (const float*)d_in[3];
    const float* bv            = (const float*)d_in[4];
    const float* Wp            = (const float*)d_in[5];
    const float* bp            = (const float*)d_in[6];
    const float* proto         = (const float*)d_in[7];
    const float* Wc            = (const float*)d_in[8];
    const float* bc            = (const float*)d_in[9];
    float* out = (float*)d_out;

    __nv_bfloat16 *ah, *al, *pah, *pal, *wvh, *wvl, *wph, *wpl;
    cudaGetSymbolAddress((void**)&ah,  g_a_hi);
    cudaGetSymbolAddress((void**)&al,  g_a_lo);
    cudaGetSymbolAddress((void**)&pah, g_pa_hi);
    cudaGetSymbolAddress((void**)&pal, g_pa_lo);
    cudaGetSymbolAddress((void**)&wvh, g_wv_hi);
    cudaGetSymbolAddress((void**)&wvl, g_wv_lo);
    cudaGetSymbolAddress((void**)&wph, g_wp_hi);
    cudaGetSymbolAddress((void**)&wpl, g_wp_lo);

    cudaFuncSetAttribute(k_gemm_mma, cudaFuncAttributeMaxDynamicSharedMemorySize, GEMM_SMEM);

    k_zero<<<1, 1>>>();
    k_split<<<4096, 256>>>(visual_tokens, ah, al, MV * H_ / 4);
    k_split<<<1024, 256>>>(phrase_states, pah, pal, MP * H_ / 4);
    k_split<<<256, 256>>>(Wv, wvh, wvl, H_ * D_ / 4);
    k_split<<<256, 256>>>(Wp, wph, wpl, H_ * D_ / 4);
    k_gemm_mma<<<MV / 128 + MP / 128, 512, GEMM_SMEM>>>(bv, bp);
    k_phrase_proto<<<MP / 8, 256>>>(proto);
    k_attention<<<dim3(8, B_), 256>>>(labels, Wc, bc, out);
    k_finalize<<<1, 1>>>(out);
}